// round 16
// baseline (speedup 1.0000x reference)
#include <cuda_runtime.h>
#include <cuda_bf16.h>
#include <cstdint>

#define BATCH 8
#define CH    128
#define HW    256
#define HS    64
#define NN    4096   // HS*HS

// Folded into Q at downsample: 0.25 (2x2 mean) * log2(e)/sqrt(128).
#define QSCALE_DS 0.031879358f

// Scratch (__device__ globals: allocation-free rule). L2-resident.
__device__ __nv_bfloat16 g_k[(size_t)BATCH*NN*CH];   // [b][n][c]
__device__ __nv_bfloat16 g_o[(size_t)BATCH*NN*CH];   // [b][n][c]
__device__ int g_kflag[BATCH*32];                    // per (batch, producer qt)

static __device__ __forceinline__ unsigned smem_u32(const void* p) {
    return (unsigned)__cvta_generic_to_shared(p);
}
static __device__ __forceinline__ float ex2f(float x) {
    float y; asm("ex2.approx.ftz.f32 %0, %1;" : "=f"(y) : "f"(x)); return y;
}
static __device__ __forceinline__ void cp16(unsigned dst, const void* src) {
    asm volatile("cp.async.cg.shared.global [%0], [%1], 16;\n" :: "r"(dst), "l"(src) : "memory");
}
static __device__ __forceinline__ void cp_commit() {
    asm volatile("cp.async.commit_group;\n" ::: "memory");
}
template<int N>
static __device__ __forceinline__ void cp_wait() {
    asm volatile("cp.async.wait_group %0;\n" :: "n"(N) : "memory");
}
static __device__ __forceinline__ void ldsm_x4(unsigned& r0, unsigned& r1, unsigned& r2, unsigned& r3, unsigned a) {
    asm volatile("ldmatrix.sync.aligned.m8n8.x4.shared.b16 {%0,%1,%2,%3}, [%4];\n"
        : "=r"(r0), "=r"(r1), "=r"(r2), "=r"(r3) : "r"(a));
}
static __device__ __forceinline__ void ldsm_x4_t(unsigned& r0, unsigned& r1, unsigned& r2, unsigned& r3, unsigned a) {
    asm volatile("ldmatrix.sync.aligned.m8n8.x4.trans.shared.b16 {%0,%1,%2,%3}, [%4];\n"
        : "=r"(r0), "=r"(r1), "=r"(r2), "=r"(r3) : "r"(a));
}
static __device__ __forceinline__ void mma16816(float* d, const unsigned* a, unsigned b0, unsigned b1) {
    asm volatile("mma.sync.aligned.m16n8k16.row.col.f32.bf16.bf16.f32 "
        "{%0,%1,%2,%3}, {%4,%5,%6,%7}, {%8,%9}, {%0,%1,%2,%3};\n"
        : "+f"(d[0]), "+f"(d[1]), "+f"(d[2]), "+f"(d[3])
        : "r"(a[0]), "r"(a[1]), "r"(a[2]), "r"(a[3]), "r"(b0), "r"(b1));
}

// Dynamic smem (bf16 element offsets):
//   sQ   : 128 x 128        @ 0      (32 KB)
//   sK0  :  64 x 128        @ 16384  (16 KB)
//   sK1  :  64 x 128        @ 24576  (16 KB)
//   sout :  64 x 132 stage  @ 32768  (16.9 KB)  (K-production transpose)
#define SQ_OFF   0
#define SK_OFF(buf) (16384 + (buf)*8192)
#define SOUT_OFF 32768
#define SMEM_DYN (82432 + 1024)

// ---------------------------------------------------------------------------
// Kernel 0: nop — shifts ncu capture window (attn lands at launch index 3).
// ---------------------------------------------------------------------------
__global__ void nop_kernel() {}

// ---------------------------------------------------------------------------
// Kernel 1: reset producer flags (each graph replay, stream-ordered pre-attn).
// ---------------------------------------------------------------------------
__global__ void reset_kernel() {
    if (threadIdx.x < BATCH*32) g_kflag[threadIdx.x] = 0;
}

// ---------------------------------------------------------------------------
// K-tile production: CTA produces spatial rows {2pq, 2pq+1} of batch b into
// g_k (2x2-mean downsample of fn), then releases its flag. CTA-uniform call.
// ---------------------------------------------------------------------------
__device__ __noinline__ void produce_k(const float* __restrict__ fn, int b, int pq,
                                       __nv_bfloat16* sout) {
    const int tid = threadIdx.x;
    const int x  = tid & 63;
    const int cq = tid >> 6;
    for (int i = 0; i < 2; ++i) {
        const int tt = 2*pq + i;     // spatial source row
        #pragma unroll 4
        for (int cb = 0; cb < CH; cb += 4) {
            const int c = cb + cq;
            const float4* p = (const float4*)(fn + (((size_t)(b*CH + c))*HW + (4*tt + 1))*HW) + x;
            float4 a0 = p[0];
            float4 a1 = p[HW/4];
            sout[x*132 + c] = __float2bfloat16(0.25f*(a0.y + a0.z + a1.y + a1.z));
        }
        __syncthreads();
        __nv_bfloat16* dbase = g_k + ((size_t)b*NN + (size_t)tt*64)*CH;
        #pragma unroll
        for (int t = tid; t < 64*32; t += 256) {
            const int x2 = t >> 5, cg = t & 31;
            *(uint2*)&dbase[(size_t)x2*CH + cg*4] = *(const uint2*)&sout[x2*132 + cg*4];
        }
        __syncthreads();
    }
    __threadfence();
    __syncthreads();
    if (tid == 0)
        asm volatile("st.release.gpu.global.u32 [%0], %1;"
                     :: "l"(g_kflag + b*32 + pq), "r"(1) : "memory");
}

static __device__ __forceinline__ void wait_kflag(int b, int pq) {
    if (threadIdx.x == 0) {
        unsigned v;
        do {
            asm volatile("ld.acquire.gpu.global.u32 %0, [%1];"
                         : "=r"(v) : "l"(g_kflag + b*32 + pq) : "memory");
        } while (!v);
    }
    __syncthreads();
}

// ---------------------------------------------------------------------------
// Kernel 2: fused downsample + flash attention (no-max softmax, V = K).
// grid (32, 8), 256 threads. All 256 CTAs resident in one wave (occ 2).
// Q downsampled directly into smem; K tiles produced lazily (rate-matched
// to consumption, 6-tile lead) so the 134MB fn read hides under the
// DRAM-idle mma/LDSM mainloop. Main loop body identical to round-11.
// ---------------------------------------------------------------------------
__global__ __launch_bounds__(256, 2) void attn_kernel(const float* __restrict__ fw,
                                                      const float* __restrict__ fn) {
    extern __shared__ __align__(16) char dsm[];
    __nv_bfloat16* sm = (__nv_bfloat16*)(((unsigned long long)dsm + 1023ull) & ~1023ull);
    __nv_bfloat16* sQ   = sm + SQ_OFF;
    __nv_bfloat16* sout = sm + SOUT_OFF;

    const int b    = blockIdx.y;
    const int qt   = blockIdx.x;
    const int tid  = threadIdx.x;
    const int warp = tid >> 5;
    const int lane = tid & 31;
    const int g    = lane >> 2;     // row within 8-group
    const int tg   = lane & 3;
    const int t4   = lane >> 3;     // 0..3
    const int r8   = lane & 7;

    // ---- upfront K production for early tiles (qt <= 3 covers tiles 0..7) ----
    if (qt <= 3) produce_k(fn, b, qt, sout);

    // ---- produce own Q tile directly into swizzled sQ (scale folded in) ----
    #pragma unroll 4
    for (int it = 0; it < 64; ++it) {
        const int item = tid + 256*it;       // 16384 = 128 ch x 128 rows
        const int c = item >> 7;
        const int r = item & 127;
        const int y = 2*qt + (r >> 6);
        const int x = r & 63;
        const float4* p = (const float4*)(fw + (((size_t)(b*CH + c))*HW + (4*y + 1))*HW) + x;
        float4 a0 = p[0];
        float4 a1 = p[HW/4];
        __nv_bfloat16 v = __float2bfloat16(QSCALE_DS*(a0.y + a0.z + a1.y + a1.z));
        const int k = c >> 3;
        sQ[r*128 + ((k ^ (r & 7)) << 3) + (c & 7)] = v;
    }
    __syncthreads();

    // ---- prefetch K tile 0 (flag-gated) ----
    wait_kflag(b, 0);
    {
        const __nv_bfloat16* Kg = g_k + (size_t)b*NN*CH;
        __nv_bfloat16* sK0 = sm + SK_OFF(0);
        #pragma unroll
        for (int i = tid; i < 1024; i += 256) {
            const int r = i >> 4, k = i & 15;
            cp16(smem_u32(sK0 + r*128 + ((k ^ (r & 7)) << 3)), Kg + (size_t)r*CH + k*8);
        }
        cp_commit();
    }

    float Oacc[16][4];
    #pragma unroll
    for (int t = 0; t < 16; ++t) { Oacc[t][0]=0.f; Oacc[t][1]=0.f; Oacc[t][2]=0.f; Oacc[t][3]=0.f; }
    float l0 = 0.f, l1 = 0.f;

    const __nv_bfloat16* Kbase = g_k + (size_t)b*NN*CH;
    const int qAddrRow = warp*16 + (lane & 15);     // ldmatrix A source row
    const int qAddrHi  = lane >> 4;                 // 0/1 -> col-chunk half
    const int prodIter = 2*qt - 6;                  // lazy production slot (qt>=4)

    for (int kt = 0; kt < 64; ++kt) {
        // lazy production of this CTA's K tiles, 6 tiles ahead of consumers
        if (qt >= 4 && kt == prodIter) produce_k(fn, b, qt, sout);

        // prefetch next K tile into the other buffer (flag-gated)
        if (kt < 63) {
            wait_kflag(b, (kt + 1) >> 1);
            const __nv_bfloat16* Kg = Kbase + (size_t)(kt + 1)*64*CH;
            __nv_bfloat16* sKn = sm + SK_OFF((kt + 1) & 1);
            #pragma unroll
            for (int i = tid; i < 1024; i += 256) {
                const int r = i >> 4, k = i & 15;
                cp16(smem_u32(sKn + r*128 + ((k ^ (r & 7)) << 3)), Kg + (size_t)r*CH + k*8);
            }
            cp_commit();
            cp_wait<1>();
        } else {
            cp_wait<0>();
        }
        __syncthreads();

        const __nv_bfloat16* sK = sm + SK_OFF(kt & 1);

        // ---- S = Q * Ktile^T  (m16 x n64 x k128 per warp) ----
        float sacc[8][4];
        #pragma unroll
        for (int t = 0; t < 8; ++t) { sacc[t][0]=0.f; sacc[t][1]=0.f; sacc[t][2]=0.f; sacc[t][3]=0.f; }

        #pragma unroll
        for (int kc = 0; kc < 8; ++kc) {
            unsigned aQ[4];
            {
                const int kchunk = kc*2 + qAddrHi;
                unsigned addr = smem_u32(&sQ[qAddrRow*128 + ((kchunk ^ (qAddrRow & 7)) << 3)]);
                ldsm_x4(aQ[0], aQ[1], aQ[2], aQ[3], addr);
            }
            #pragma unroll
            for (int p2 = 0; p2 < 4; ++p2) {
                const int m  = (2*p2 + (t4 >> 1))*8 + r8;
                const int cc = kc*16 + (t4 & 1)*8;
                unsigned addr = smem_u32(&sK[m*128 + (((cc >> 3) ^ (m & 7)) << 3)]);
                unsigned r0, r1, r2, r3;
                ldsm_x4(r0, r1, r2, r3, addr);
                mma16816(sacc[2*p2],     aQ, r0, r1);
                mma16816(sacc[2*p2 + 1], aQ, r2, r3);
            }
        }

        // ---- p = exp2(s)  (log2e/sqrt(C) folded into Q); no max, no rescale ----
        unsigned aP[4][4];
        #pragma unroll
        for (int t = 0; t < 8; ++t) {
            const float p0 = ex2f(sacc[t][0]);
            const float p1 = ex2f(sacc[t][1]);
            const float p2 = ex2f(sacc[t][2]);
            const float p3 = ex2f(sacc[t][3]);
            l0 += p0 + p1;
            l1 += p2 + p3;
            const int kk = t >> 1, hi = t & 1;
            __nv_bfloat162 w01 = __floats2bfloat162_rn(p0, p1);
            __nv_bfloat162 w23 = __floats2bfloat162_rn(p2, p3);
            aP[kk][hi*2 + 0] = *reinterpret_cast<unsigned*>(&w01);
            aP[kk][hi*2 + 1] = *reinterpret_cast<unsigned*>(&w23);
        }

        // ---- O += P * Vtile (V = K), B frags via ldmatrix.trans ----
        #pragma unroll
        for (int kk = 0; kk < 4; ++kk) {
            #pragma unroll
            for (int cp = 0; cp < 8; ++cp) {
                const int m  = kk*16 + (t4 & 1)*8 + r8;
                const int cc = (cp*2 + (t4 >> 1))*8;
                unsigned addr = smem_u32(&sK[m*128 + (((cc >> 3) ^ (m & 7)) << 3)]);
                unsigned r0, r1, r2, r3;
                ldsm_x4_t(r0, r1, r2, r3, addr);
                mma16816(Oacc[2*cp],     aP[kk], r0, r1);
                mma16816(Oacc[2*cp + 1], aP[kk], r2, r3);
            }
        }
        __syncthreads();
    }

    // ---- epilogue: reduce l across quad, normalize, store bf16 [b][n][c] ----
    l0 += __shfl_xor_sync(0xffffffffu, l0, 1);
    l0 += __shfl_xor_sync(0xffffffffu, l0, 2);
    l1 += __shfl_xor_sync(0xffffffffu, l1, 1);
    l1 += __shfl_xor_sync(0xffffffffu, l1, 2);
    const float inv0 = 1.f / l0;
    const float inv1 = 1.f / l1;

    const int qrow = qt*128 + warp*16;
    __nv_bfloat16* Ob = g_o + ((size_t)b*NN + qrow)*CH;
    #pragma unroll
    for (int ct = 0; ct < 16; ++ct) {
        __nv_bfloat162 v0 = __floats2bfloat162_rn(Oacc[ct][0]*inv0, Oacc[ct][1]*inv0);
        __nv_bfloat162 v1 = __floats2bfloat162_rn(Oacc[ct][2]*inv1, Oacc[ct][3]*inv1);
        *(__nv_bfloat162*)&Ob[(size_t)(g    )*CH + ct*8 + tg*2] = v0;
        *(__nv_bfloat162*)&Ob[(size_t)(g + 8)*CH + ct*8 + tg*2] = v1;
    }
}

// ---------------------------------------------------------------------------
// Kernel 3: 4x bilinear upsample of g_o + residual add. grid (256,8), 256 thr.
// (round-11 version: y-interp fused into float smem plane, float4 hot loop.)
// ---------------------------------------------------------------------------
__global__ __launch_bounds__(256) void up_kernel(const float* __restrict__ fw,
                                                 float* __restrict__ out) {
    __shared__ float sv[CH][HS + 2];   // [c][x+1], edge-duplicated
    const int Y   = blockIdx.x;
    const int b   = blockIdx.y;
    const int tid = threadIdx.x;

    const float yf = (Y + 0.5f)*0.25f - 0.5f;
    const int   iy = (int)floorf(yf);
    const float ty = yf - (float)iy;
    const int r0 = max(iy, 0), r1 = min(iy + 1, HS - 1);
    const float wy0 = 1.f - ty, wy1 = ty;

    for (int t = tid; t < 64*32; t += 256) {
        const int cg = t & 31;            // channel group (4 ch)
        const int x  = t >> 5;            // source col
        const __nv_bfloat16* p0 = g_o + ((size_t)b*NN + (size_t)r0*64 + x)*CH + cg*4;
        const __nv_bfloat16* p1 = g_o + ((size_t)b*NN + (size_t)r1*64 + x)*CH + cg*4;
        uint2 v0 = *(const uint2*)p0;
        uint2 v1 = *(const uint2*)p1;
        float2 a0 = __bfloat1622float2(*reinterpret_cast<__nv_bfloat162*>(&v0.x));
        float2 a1 = __bfloat1622float2(*reinterpret_cast<__nv_bfloat162*>(&v0.y));
        float2 b0 = __bfloat1622float2(*reinterpret_cast<__nv_bfloat162*>(&v1.x));
        float2 b1 = __bfloat1622float2(*reinterpret_cast<__nv_bfloat162*>(&v1.y));
        sv[cg*4 + 0][x + 1] = wy0*a0.x + wy1*b0.x;
        sv[cg*4 + 1][x + 1] = wy0*a0.y + wy1*b0.y;
        sv[cg*4 + 2][x + 1] = wy0*a1.x + wy1*b1.x;
        sv[cg*4 + 3][x + 1] = wy0*a1.y + wy1*b1.y;
    }
    __syncthreads();
    if (tid < CH) {             // duplicate edge columns (clamp-free hot loop)
        sv[tid][0]      = sv[tid][1];
        sv[tid][HS + 1] = sv[tid][HS];
    }
    __syncthreads();

    const int xg    = tid & 63;           // output group: X = 4*xg .. 4*xg+3
    const int cbase = tid >> 6;           // 0..3
    const float4* fwv  = (const float4*)(fw  + (((size_t)(b*CH + cbase))*HW + Y)*HW) + xg;
    float4*       outv = (float4*)      (out + (((size_t)(b*CH + cbase))*HW + Y)*HW) + xg;
    const size_t cstride4 = (size_t)4*HW*HW/4;   // float4 stride for c += 4

    #pragma unroll 4
    for (int it = 0; it < 32; ++it) {
        const int c = cbase + it*4;
        const float svl = sv[c][xg];
        const float svc = sv[c][xg + 1];
        const float svr = sv[c][xg + 2];
        const float4 f = fwv[it*cstride4];
        float4 o;
        o.x = f.x + 0.375f*svl + 0.625f*svc;
        o.y = f.y + 0.125f*svl + 0.875f*svc;
        o.z = f.z + 0.875f*svc + 0.125f*svr;
        o.w = f.w + 0.625f*svc + 0.375f*svr;
        outv[it*cstride4] = o;
    }
}

// ---------------------------------------------------------------------------
extern "C" void kernel_launch(void* const* d_in, const int* in_sizes, int n_in,
                              void* d_out, int out_size) {
    (void)in_sizes; (void)n_in; (void)out_size;
    const float* fw = (const float*)d_in[0];   // feat_wide
    const float* fn = (const float*)d_in[1];   // feat_narrow
    float* out = (float*)d_out;

    cudaFuncSetAttribute(attn_kernel, cudaFuncAttributeMaxDynamicSharedMemorySize, SMEM_DYN);

    nop_kernel<<<1, 32>>>();                            // index 0
    reset_kernel<<<1, 256>>>();                         // index 1 (flag reset)
    nop_kernel<<<1, 32>>>();                            // index 2
    attn_kernel<<<dim3(32, 8), 256, SMEM_DYN>>>(fw, fn);// index 3 <- ncu slot
    up_kernel<<<dim3(256, 8), 256>>>(fw, out);          // index 4
}

// round 17
// speedup vs baseline: 1.5336x; 1.5336x over previous
#include <cuda_runtime.h>
#include <cuda_bf16.h>
#include <cstdint>

#define BATCH 8
#define CH    128
#define HW    256
#define HS    64
#define NN    4096   // HS*HS

// Folded into Q at downsample: 0.25 (2x2 mean) * log2(e)/sqrt(128).
#define QSCALE_DS 0.031879358f

// Scratch (__device__ globals: allocation-free rule). L2-resident (8 MB each).
__device__ __nv_bfloat16 g_q[(size_t)BATCH*NN*CH];   // [b][n][c], pre-scaled
__device__ __nv_bfloat16 g_k[(size_t)BATCH*NN*CH];   // [b][n][c]
__device__ __nv_bfloat16 g_o[(size_t)BATCH*NN*CH];   // [b][n][c]

static __device__ __forceinline__ unsigned smem_u32(const void* p) {
    return (unsigned)__cvta_generic_to_shared(p);
}
static __device__ __forceinline__ float ex2f(float x) {
    float y; asm("ex2.approx.ftz.f32 %0, %1;" : "=f"(y) : "f"(x)); return y;
}
static __device__ __forceinline__ void cp16(unsigned dst, const void* src) {
    asm volatile("cp.async.cg.shared.global [%0], [%1], 16;\n" :: "r"(dst), "l"(src) : "memory");
}
static __device__ __forceinline__ void cp_commit() {
    asm volatile("cp.async.commit_group;\n" ::: "memory");
}
template<int N>
static __device__ __forceinline__ void cp_wait() {
    asm volatile("cp.async.wait_group %0;\n" :: "n"(N) : "memory");
}
static __device__ __forceinline__ void ldsm_x4(unsigned& r0, unsigned& r1, unsigned& r2, unsigned& r3, unsigned a) {
    asm volatile("ldmatrix.sync.aligned.m8n8.x4.shared.b16 {%0,%1,%2,%3}, [%4];\n"
        : "=r"(r0), "=r"(r1), "=r"(r2), "=r"(r3) : "r"(a));
}
static __device__ __forceinline__ void ldsm_x4_t(unsigned& r0, unsigned& r1, unsigned& r2, unsigned& r3, unsigned a) {
    asm volatile("ldmatrix.sync.aligned.m8n8.x4.trans.shared.b16 {%0,%1,%2,%3}, [%4];\n"
        : "=r"(r0), "=r"(r1), "=r"(r2), "=r"(r3) : "r"(a));
}
static __device__ __forceinline__ void mma16816(float* d, const unsigned* a, unsigned b0, unsigned b1) {
    asm volatile("mma.sync.aligned.m16n8k16.row.col.f32.bf16.bf16.f32 "
        "{%0,%1,%2,%3}, {%4,%5,%6,%7}, {%8,%9}, {%0,%1,%2,%3};\n"
        : "+f"(d[0]), "+f"(d[1]), "+f"(d[2]), "+f"(d[3])
        : "r"(a[0]), "r"(a[1]), "r"(a[2]), "r"(a[3]), "r"(b0), "r"(b1));
}

// Dynamic smem for attn (bf16 elements) — proven layout:
//   sQ  : 128 x 128 @ 0        (32 KB)
//   sK0 :  64 x 128 @ 16384    (16 KB)
//   sK1 :  64 x 128 @ 24576    (16 KB)
#define SQ_OFF  0
#define SK_OFF(buf) (16384 + (buf)*8192)
#define SMEM_DYN (65536 + 1024)

// ---------------------------------------------------------------------------
// Kernel 1: 0.25x bilinear downsample == mean of center 2x2 block.
// float4 load of the aligned 16B group (use .y/.z). grid (64, 8, 4), 256 thr.
// (measured 49.5us, 71% DRAM — at its sector-traffic floor)
// ---------------------------------------------------------------------------
__global__ __launch_bounds__(256) void ds_kernel(const float* __restrict__ fw,
                                                 const float* __restrict__ fn) {
    __shared__ __nv_bfloat16 sout[64][36];
    const int i   = blockIdx.x;
    const int b   = blockIdx.y;
    const int c0  = blockIdx.z * 32;          // channel-quarter base
    const int tid = threadIdx.x;
    const int j   = tid & 63;
    const int cq  = tid >> 6;

    for (int pass = 0; pass < 2; ++pass) {
        const float* src = pass ? fn : fw;
        __nv_bfloat16* dst = pass ? g_k : g_q;
        const float sc = pass ? 0.25f : QSCALE_DS;

        #pragma unroll
        for (int cb = 0; cb < 32; cb += 4) {
            const int cl = cb + cq;           // local channel 0..31
            const float4* p = (const float4*)(src + (((size_t)(b*CH + c0 + cl))*HW + (4*i + 1))*HW) + j;
            float4 a0 = p[0];                 // row 4i+1, cols 4j..4j+3
            float4 a1 = p[HW/4];              // row 4i+2
            sout[j][cl] = __float2bfloat16(sc * (a0.y + a0.z + a1.y + a1.z));
        }
        __syncthreads();
        __nv_bfloat16* dbase = dst + ((size_t)b*NN + (size_t)i*64)*CH + c0;
        #pragma unroll
        for (int t = tid; t < 64*8; t += 256) {
            const int j2 = t >> 3, cg = t & 7;
            *(uint2*)&dbase[(size_t)j2*CH + cg*4] = *(const uint2*)&sout[j2][cg*4];
        }
        __syncthreads();
    }
}

// ---------------------------------------------------------------------------
// Kernel 2: flash attention, no-max softmax (logits bounded), V = K.
// grid (32, 8), 256 threads = 8 warps x 16 query rows. occ=2 -> single wave.
// (EXACT round-11 structure — measured 204.6us, reproduced 204.3us.)
// ---------------------------------------------------------------------------
__global__ __launch_bounds__(256, 2) void attn_kernel() {
    extern __shared__ __align__(16) char dsm[];
    __nv_bfloat16* sm = (__nv_bfloat16*)(((unsigned long long)dsm + 1023ull) & ~1023ull);
    __nv_bfloat16* sQ = sm + SQ_OFF;

    const int b    = blockIdx.y;
    const int qt   = blockIdx.x;
    const int tid  = threadIdx.x;
    const int warp = tid >> 5;
    const int lane = tid & 31;
    const int g    = lane >> 2;     // row within 8-group
    const int tg   = lane & 3;
    const int t4   = lane >> 3;     // 0..3
    const int r8   = lane & 7;

    // ---- prologue: stage Q (128x128) and K tile 0 (64x128), swizzled ----
    {
        const __nv_bfloat16* Qg = g_q + ((size_t)b*NN + (size_t)qt*128)*CH;
        #pragma unroll
        for (int i = tid; i < 2048; i += 256) {     // 128 rows x 16 chunks
            const int r = i >> 4, k = i & 15;
            cp16(smem_u32(sQ + r*128 + ((k ^ (r & 7)) << 3)), Qg + (size_t)r*CH + k*8);
        }
        const __nv_bfloat16* Kg = g_k + (size_t)b*NN*CH;
        __nv_bfloat16* sK0 = sm + SK_OFF(0);
        #pragma unroll
        for (int i = tid; i < 1024; i += 256) {     // 64 rows x 16 chunks
            const int r = i >> 4, k = i & 15;
            cp16(smem_u32(sK0 + r*128 + ((k ^ (r & 7)) << 3)), Kg + (size_t)r*CH + k*8);
        }
        cp_commit();
    }

    float Oacc[16][4];
    #pragma unroll
    for (int t = 0; t < 16; ++t) { Oacc[t][0]=0.f; Oacc[t][1]=0.f; Oacc[t][2]=0.f; Oacc[t][3]=0.f; }
    float l0 = 0.f, l1 = 0.f;

    const __nv_bfloat16* Kbase = g_k + (size_t)b*NN*CH;
    const int qAddrRow = warp*16 + (lane & 15);     // ldmatrix A source row
    const int qAddrHi  = lane >> 4;                 // 0/1 -> col-chunk half

    for (int kt = 0; kt < 64; ++kt) {
        // prefetch next K tile into the other buffer
        if (kt < 63) {
            const __nv_bfloat16* Kg = Kbase + (size_t)(kt + 1)*64*CH;
            __nv_bfloat16* sKn = sm + SK_OFF((kt + 1) & 1);
            #pragma unroll
            for (int i = tid; i < 1024; i += 256) {
                const int r = i >> 4, k = i & 15;
                cp16(smem_u32(sKn + r*128 + ((k ^ (r & 7)) << 3)), Kg + (size_t)r*CH + k*8);
            }
            cp_commit();
            cp_wait<1>();
        } else {
            cp_wait<0>();
        }
        __syncthreads();

        const __nv_bfloat16* sK = sm + SK_OFF(kt & 1);

        // ---- S = Q * Ktile^T  (m16 x n64 x k128 per warp) ----
        float sacc[8][4];
        #pragma unroll
        for (int t = 0; t < 8; ++t) { sacc[t][0]=0.f; sacc[t][1]=0.f; sacc[t][2]=0.f; sacc[t][3]=0.f; }

        #pragma unroll
        for (int kc = 0; kc < 8; ++kc) {
            unsigned aQ[4];
            {
                const int kchunk = kc*2 + qAddrHi;
                unsigned addr = smem_u32(&sQ[qAddrRow*128 + ((kchunk ^ (qAddrRow & 7)) << 3)]);
                ldsm_x4(aQ[0], aQ[1], aQ[2], aQ[3], addr);
            }
            #pragma unroll
            for (int p2 = 0; p2 < 4; ++p2) {
                const int m  = (2*p2 + (t4 >> 1))*8 + r8;
                const int cc = kc*16 + (t4 & 1)*8;
                unsigned addr = smem_u32(&sK[m*128 + (((cc >> 3) ^ (m & 7)) << 3)]);
                unsigned r0, r1, r2, r3;
                ldsm_x4(r0, r1, r2, r3, addr);
                mma16816(sacc[2*p2],     aQ, r0, r1);
                mma16816(sacc[2*p2 + 1], aQ, r2, r3);
            }
        }

        // ---- p = exp2(s)  (log2e/sqrt(C) folded into Q); no max, no rescale ----
        unsigned aP[4][4];
        #pragma unroll
        for (int t = 0; t < 8; ++t) {
            const float p0 = ex2f(sacc[t][0]);
            const float p1 = ex2f(sacc[t][1]);
            const float p2 = ex2f(sacc[t][2]);
            const float p3 = ex2f(sacc[t][3]);
            l0 += p0 + p1;
            l1 += p2 + p3;
            const int kk = t >> 1, hi = t & 1;
            __nv_bfloat162 w01 = __floats2bfloat162_rn(p0, p1);
            __nv_bfloat162 w23 = __floats2bfloat162_rn(p2, p3);
            aP[kk][hi*2 + 0] = *reinterpret_cast<unsigned*>(&w01);
            aP[kk][hi*2 + 1] = *reinterpret_cast<unsigned*>(&w23);
        }

        // ---- O += P * Vtile (V = K), B frags via ldmatrix.trans ----
        #pragma unroll
        for (int kk = 0; kk < 4; ++kk) {
            #pragma unroll
            for (int cp = 0; cp < 8; ++cp) {
                const int m  = kk*16 + (t4 & 1)*8 + r8;
                const int cc = (cp*2 + (t4 >> 1))*8;
                unsigned addr = smem_u32(&sK[m*128 + (((cc >> 3) ^ (m & 7)) << 3)]);
                unsigned r0, r1, r2, r3;
                ldsm_x4_t(r0, r1, r2, r3, addr);
                mma16816(Oacc[2*cp],     aP[kk], r0, r1);
                mma16816(Oacc[2*cp + 1], aP[kk], r2, r3);
            }
        }
        __syncthreads();
    }

    // ---- epilogue: reduce l across quad, normalize, store bf16 [b][n][c] ----
    l0 += __shfl_xor_sync(0xffffffffu, l0, 1);
    l0 += __shfl_xor_sync(0xffffffffu, l0, 2);
    l1 += __shfl_xor_sync(0xffffffffu, l1, 1);
    l1 += __shfl_xor_sync(0xffffffffu, l1, 2);
    const float inv0 = 1.f / l0;
    const float inv1 = 1.f / l1;

    const int qrow = qt*128 + warp*16;
    __nv_bfloat16* Ob = g_o + ((size_t)b*NN + qrow)*CH;
    #pragma unroll
    for (int ct = 0; ct < 16; ++ct) {
        __nv_bfloat162 v0 = __floats2bfloat162_rn(Oacc[ct][0]*inv0, Oacc[ct][1]*inv0);
        __nv_bfloat162 v1 = __floats2bfloat162_rn(Oacc[ct][2]*inv1, Oacc[ct][3]*inv1);
        *(__nv_bfloat162*)&Ob[(size_t)(g    )*CH + ct*8 + tg*2] = v0;
        *(__nv_bfloat162*)&Ob[(size_t)(g + 8)*CH + ct*8 + tg*2] = v1;
    }
}

// ---------------------------------------------------------------------------
// Kernel 3: 4x bilinear upsample of g_o + residual add. grid (256,8), 256 thr.
// y-interp fused into float smem plane; vectorized float4 hot loop.
// (round-11 version — fastest measured total)
// ---------------------------------------------------------------------------
__global__ __launch_bounds__(256) void up_kernel(const float* __restrict__ fw,
                                                 float* __restrict__ out) {
    __shared__ float sv[CH][HS + 2];   // [c][x+1], edge-duplicated
    const int Y   = blockIdx.x;
    const int b   = blockIdx.y;
    const int tid = threadIdx.x;

    const float yf = (Y + 0.5f)*0.25f - 0.5f;
    const int   iy = (int)floorf(yf);
    const float ty = yf - (float)iy;
    const int r0 = max(iy, 0), r1 = min(iy + 1, HS - 1);
    const float wy0 = 1.f - ty, wy1 = ty;

    for (int t = tid; t < 64*32; t += 256) {
        const int cg = t & 31;            // channel group (4 ch)
        const int x  = t >> 5;            // source col
        const __nv_bfloat16* p0 = g_o + ((size_t)b*NN + (size_t)r0*64 + x)*CH + cg*4;
        const __nv_bfloat16* p1 = g_o + ((size_t)b*NN + (size_t)r1*64 + x)*CH + cg*4;
        uint2 v0 = *(const uint2*)p0;
        uint2 v1 = *(const uint2*)p1;
        float2 a0 = __bfloat1622float2(*reinterpret_cast<__nv_bfloat162*>(&v0.x));
        float2 a1 = __bfloat1622float2(*reinterpret_cast<__nv_bfloat162*>(&v0.y));
        float2 b0 = __bfloat1622float2(*reinterpret_cast<__nv_bfloat162*>(&v1.x));
        float2 b1 = __bfloat1622float2(*reinterpret_cast<__nv_bfloat162*>(&v1.y));
        sv[cg*4 + 0][x + 1] = wy0*a0.x + wy1*b0.x;
        sv[cg*4 + 1][x + 1] = wy0*a0.y + wy1*b0.y;
        sv[cg*4 + 2][x + 1] = wy0*a1.x + wy1*b1.x;
        sv[cg*4 + 3][x + 1] = wy0*a1.y + wy1*b1.y;
    }
    __syncthreads();
    if (tid < CH) {             // duplicate edge columns (clamp-free hot loop)
        sv[tid][0]      = sv[tid][1];
        sv[tid][HS + 1] = sv[tid][HS];
    }
    __syncthreads();

    const int xg    = tid & 63;           // output group: X = 4*xg .. 4*xg+3
    const int cbase = tid >> 6;           // 0..3
    const float4* fwv  = (const float4*)(fw  + (((size_t)(b*CH + cbase))*HW + Y)*HW) + xg;
    float4*       outv = (float4*)      (out + (((size_t)(b*CH + cbase))*HW + Y)*HW) + xg;
    const size_t cstride4 = (size_t)4*HW*HW/4;   // float4 stride for c += 4

    #pragma unroll 4
    for (int it = 0; it < 32; ++it) {
        const int c = cbase + it*4;
        const float svl = sv[c][xg];
        const float svc = sv[c][xg + 1];
        const float svr = sv[c][xg + 2];
        const float4 f = fwv[it*cstride4];
        float4 o;
        o.x = f.x + 0.375f*svl + 0.625f*svc;
        o.y = f.y + 0.125f*svl + 0.875f*svc;
        o.z = f.z + 0.875f*svc + 0.125f*svr;
        o.w = f.w + 0.625f*svc + 0.375f*svr;
        outv[it*cstride4] = o;
    }
}

// ---------------------------------------------------------------------------
extern "C" void kernel_launch(void* const* d_in, const int* in_sizes, int n_in,
                              void* d_out, int out_size) {
    (void)in_sizes; (void)n_in; (void)out_size;
    const float* fw = (const float*)d_in[0];   // feat_wide
    const float* fn = (const float*)d_in[1];   // feat_narrow
    float* out = (float*)d_out;

    cudaFuncSetAttribute(attn_kernel, cudaFuncAttributeMaxDynamicSharedMemorySize, SMEM_DYN);

    ds_kernel<<<dim3(64, 8, 4), 256>>>(fw, fn);
    attn_kernel<<<dim3(32, 8), 256, SMEM_DYN>>>();
    up_kernel<<<dim3(256, 8), 256>>>(fw, out);
}